// round 2
// baseline (speedup 1.0000x reference)
#include <cuda_runtime.h>
#include <math.h>

#define BATCH   8
#define NPTS    8192
#define NPOINT  2048
#define NSAMPLE 32

// ---------------- device scratch (no allocs allowed) ----------------
__device__ float g_W1t[3 * 64];     // [c][o]
__device__ float g_W2t[64 * 64];    // [c][o]
__device__ float g_W3t[64 * 128];   // [c][o]
__device__ float g_B[256];          // b1f[64] | b2f[64] | b3f[128]

// ---------------- prep: fold BN into weights ----------------
__global__ void prep_kernel(
    const float* __restrict__ w1, const float* __restrict__ b1, const float* __restrict__ g1,
    const float* __restrict__ be1, const float* __restrict__ m1, const float* __restrict__ v1,
    const float* __restrict__ w2, const float* __restrict__ b2, const float* __restrict__ g2,
    const float* __restrict__ be2, const float* __restrict__ m2, const float* __restrict__ v2,
    const float* __restrict__ w3, const float* __restrict__ b3, const float* __restrict__ g3,
    const float* __restrict__ be3, const float* __restrict__ m3, const float* __restrict__ v3)
{
    int t = threadIdx.x;
    if (t < 64) {
        float s1 = g1[t] / sqrtf(v1[t] + 1e-5f);
        g_B[t] = (b1[t] - m1[t]) * s1 + be1[t];
        for (int c = 0; c < 3; c++) g_W1t[c * 64 + t] = w1[t * 3 + c] * s1;

        float s2 = g2[t] / sqrtf(v2[t] + 1e-5f);
        g_B[64 + t] = (b2[t] - m2[t]) * s2 + be2[t];
        for (int c = 0; c < 64; c++) g_W2t[c * 64 + t] = w2[t * 64 + c] * s2;
    }
    if (t < 128) {
        float s3 = g3[t] / sqrtf(v3[t] + 1e-5f);
        g_B[128 + t] = (b3[t] - m3[t]) * s3 + be3[t];
        for (int c = 0; c < 64; c++) g_W3t[c * 128 + t] = w3[t * 64 + c] * s3;
    }
}

// ---------------- FPS: one CTA per batch ----------------
// Coords + dists live in registers; shared coord mirror only for centroid lookup.
extern __shared__ float fps_sm[];

__global__ __launch_bounds__(1024, 1) void fps_kernel(
    const float* __restrict__ xyz, float* __restrict__ newxyz)
{
    const int b = blockIdx.x;
    const float* P = xyz + (size_t)b * NPTS * 3;
    float* O = newxyz + (size_t)b * NPOINT * 3;
    const int tid = threadIdx.x;
    const int lane = tid & 31, wid = tid >> 5;

    float* shx = fps_sm;              // [8192]
    float* shy = shx + NPTS;          // [8192]
    float* shz = shy + NPTS;          // [8192]

    float px[8], py[8], pz[8], d[8];
#pragma unroll
    for (int j = 0; j < 8; j++) {
        int p = tid + 1024 * j;
        float x = P[3 * p], y = P[3 * p + 1], z = P[3 * p + 2];
        px[j] = x; py[j] = y; pz[j] = z;
        shx[p] = x; shy[p] = y; shz[p] = z;
    }

    __shared__ float s_val[32];
    __shared__ int   s_idx[32];
    __shared__ int   s_ci;

    float cx = P[0], cy = P[1], cz = P[2];
    if (tid == 0) { O[0] = cx; O[1] = cy; O[2] = cz; }

    // init dists vs point 0 (exact: no FMA contraction)
#pragma unroll
    for (int j = 0; j < 8; j++) {
        float dx = __fadd_rn(px[j], -cx);
        float dy = __fadd_rn(py[j], -cy);
        float dz = __fadd_rn(pz[j], -cz);
        d[j] = __fadd_rn(__fadd_rn(__fmul_rn(dx, dx), __fmul_rn(dy, dy)), __fmul_rn(dz, dz));
    }
    __syncthreads();   // shared coord mirror ready

    for (int it = 1; it < NPOINT; ++it) {
        float bv = -1.0f; int bi = 0;
#pragma unroll
        for (int j = 0; j < 8; j++) {
            float dx = __fadd_rn(px[j], -cx);
            float dy = __fadd_rn(py[j], -cy);
            float dz = __fadd_rn(pz[j], -cz);
            float cand = __fadd_rn(__fadd_rn(__fmul_rn(dx, dx), __fmul_rn(dy, dy)),
                                   __fmul_rn(dz, dz));
            float nd = fminf(d[j], cand);
            d[j] = nd;
            if (nd > bv) { bv = nd; bi = tid + 1024 * j; }   // strict > keeps lowest index
        }
        // warp argmax (tie -> lower index)
#pragma unroll
        for (int off = 16; off >= 1; off >>= 1) {
            float ov = __shfl_down_sync(0xffffffffu, bv, off);
            int   oi = __shfl_down_sync(0xffffffffu, bi, off);
            if (ov > bv || (ov == bv && oi < bi)) { bv = ov; bi = oi; }
        }
        if (lane == 0) { s_val[wid] = bv; s_idx[wid] = bi; }
        __syncthreads();
        if (wid == 0) {
            bv = s_val[lane]; bi = s_idx[lane];
#pragma unroll
            for (int off = 16; off >= 1; off >>= 1) {
                float ov = __shfl_down_sync(0xffffffffu, bv, off);
                int   oi = __shfl_down_sync(0xffffffffu, bi, off);
                if (ov > bv || (ov == bv && oi < bi)) { bv = ov; bi = oi; }
            }
            if (lane == 0) s_ci = bi;
        }
        __syncthreads();
        int ci = s_ci;
        cx = shx[ci]; cy = shy[ci]; cz = shz[ci];
        if (tid == 0) { float* o = O + 3 * it; o[0] = cx; o[1] = cy; o[2] = cz; }
    }
}

// ---------------- fused ball-query + MLP + maxpool ----------------
// One warp per centroid; 8 warps (8 consecutive m) per block.
extern __shared__ float fus_sm[];

__global__ __launch_bounds__(256) void fused_kernel(
    const float* __restrict__ xyz, const float* __restrict__ newxyz,
    float* __restrict__ out2)
{
    // shared layout (bytes): W2t 16384 | W3t 32768 | W1t 768 | B 1024 | stage 4096 | nb 1024
    float* W2t   = fus_sm;                  // 64*64
    float* W3t   = W2t + 64 * 64;           // 64*128
    float* W1t   = W3t + 64 * 128;          // 3*64
    float* Bsh   = W1t + 192;               // 256
    float* stage = Bsh + 256;               // 128*8
    int*   nb    = (int*)(stage + 128 * 8); // 8*32

    const int tid = threadIdx.x;
    for (int i = tid; i < 64 * 64; i += 256)  W2t[i] = g_W2t[i];
    for (int i = tid; i < 64 * 128; i += 256) W3t[i] = g_W3t[i];
    if (tid < 192) W1t[tid] = g_W1t[tid];
    if (tid < 256) Bsh[tid] = g_B[tid];
    __syncthreads();

    const int w = tid >> 5, lane = tid & 31;
    const int b = blockIdx.x >> 8;                  // 256 blocks per batch
    const int m0 = (blockIdx.x & 255) * 8;
    const int m = m0 + w;

    const float* P = xyz + (size_t)b * NPTS * 3;
    const float* C = newxyz + ((size_t)b * NPOINT + m) * 3;
    const float cx = C[0], cy = C[1], cz = C[2];

    // ---- ball query: first 32 in-radius indices in ascending order ----
    const float R2 = (float)(0.2 * 0.2);   // matches ref double->f32 rounding
    int* mynb = nb + w * 32;
    int cnt = 0;
    for (int base = 0; base < NPTS && cnt < NSAMPLE; base += 32) {
        int p = base + lane;
        float x = P[3 * p], y = P[3 * p + 1], z = P[3 * p + 2];
        float dx = __fadd_rn(x, -cx), dy = __fadd_rn(y, -cy), dz = __fadd_rn(z, -cz);
        float s = __fadd_rn(__fadd_rn(__fmul_rn(dx, dx), __fmul_rn(dy, dy)), __fmul_rn(dz, dz));
        bool in = (s <= R2);
        unsigned msk = __ballot_sync(0xffffffffu, in);
        int pos = cnt + __popc(msk & ((1u << lane) - 1u));
        if (in && pos < NSAMPLE) mynb[pos] = p;
        cnt += __popc(msk);
    }
    __syncwarp();
    int src = (cnt >= NSAMPLE) ? lane : (lane % cnt);   // cnt >= 1 always
    int g = mynb[src];

    float gx = P[3 * g] - cx, gy = P[3 * g + 1] - cy, gz = P[3 * g + 2] - cz;

    // ---- layer 1: 3 -> 64 ----
    float h1[64];
#pragma unroll
    for (int o = 0; o < 64; o++) h1[o] = fmaf(gx, W1t[o], Bsh[o]);
#pragma unroll
    for (int o = 0; o < 64; o++) h1[o] = fmaf(gy, W1t[64 + o], h1[o]);
#pragma unroll
    for (int o = 0; o < 64; o++) h1[o] = fmaxf(fmaf(gz, W1t[128 + o], h1[o]), 0.0f);

    // ---- layer 2: 64 -> 64 ----
    float h2[64];
#pragma unroll
    for (int o = 0; o < 64; o++) h2[o] = Bsh[64 + o];
#pragma unroll
    for (int c = 0; c < 64; c++) {
        float hc = h1[c];
        const float4* wr = (const float4*)(W2t + c * 64);
#pragma unroll
        for (int q = 0; q < 16; q++) {
            float4 wv = wr[q];
            h2[4 * q + 0] = fmaf(hc, wv.x, h2[4 * q + 0]);
            h2[4 * q + 1] = fmaf(hc, wv.y, h2[4 * q + 1]);
            h2[4 * q + 2] = fmaf(hc, wv.z, h2[4 * q + 2]);
            h2[4 * q + 3] = fmaf(hc, wv.w, h2[4 * q + 3]);
        }
    }
#pragma unroll
    for (int o = 0; o < 64; o++) h2[o] = fmaxf(h2[o], 0.0f);

    // ---- layer 3: 64 -> 128, two halves of 64, with warp maxpool ----
#pragma unroll
    for (int half = 0; half < 2; half++) {
        float acc[64];
#pragma unroll
        for (int o = 0; o < 64; o++) acc[o] = Bsh[128 + half * 64 + o];
#pragma unroll
        for (int c = 0; c < 64; c++) {
            float hc = h2[c];
            const float4* wr = (const float4*)(W3t + c * 128 + half * 64);
#pragma unroll
            for (int q = 0; q < 16; q++) {
                float4 wv = wr[q];
                acc[4 * q + 0] = fmaf(hc, wv.x, acc[4 * q + 0]);
                acc[4 * q + 1] = fmaf(hc, wv.y, acc[4 * q + 1]);
                acc[4 * q + 2] = fmaf(hc, wv.z, acc[4 * q + 2]);
                acc[4 * q + 3] = fmaf(hc, wv.w, acc[4 * q + 3]);
            }
        }
#pragma unroll
        for (int o = 0; o < 64; o++) acc[o] = fmaxf(acc[o], 0.0f);
        // maxpool over 32 samples (lanes); result lands in lane 0
#pragma unroll
        for (int off = 16; off >= 1; off >>= 1) {
#pragma unroll
            for (int o = 0; o < 64; o++)
                acc[o] = fmaxf(acc[o], __shfl_down_sync(0xffffffffu, acc[o], off));
        }
        if (lane == 0) {
#pragma unroll
            for (int o = 0; o < 64; o++) stage[(half * 64 + o) * 8 + w] = acc[o];
        }
    }
    __syncthreads();

    // coalesced-ish transpose write: out2[b][ch][m0..m0+7]
    {
        int ch = tid >> 1, part = tid & 1;   // 256 threads -> 128 rows x 2 float4
        float4 v = ((const float4*)stage)[tid];
        *(float4*)(out2 + ((size_t)(b * 128 + ch)) * NPOINT + m0 + part * 4) = v;
    }
}

// ---------------- launch ----------------
extern "C" void kernel_launch(void* const* d_in, const int* in_sizes, int n_in,
                              void* d_out, int out_size)
{
    const float* xyz = (const float*)d_in[0];
    const float* w1 = (const float*)d_in[1];  const float* b1 = (const float*)d_in[2];
    const float* g1 = (const float*)d_in[3];  const float* be1 = (const float*)d_in[4];
    const float* m1 = (const float*)d_in[5];  const float* v1 = (const float*)d_in[6];
    const float* w2 = (const float*)d_in[7];  const float* b2 = (const float*)d_in[8];
    const float* g2 = (const float*)d_in[9];  const float* be2 = (const float*)d_in[10];
    const float* m2 = (const float*)d_in[11]; const float* v2 = (const float*)d_in[12];
    const float* w3 = (const float*)d_in[13]; const float* b3 = (const float*)d_in[14];
    const float* g3 = (const float*)d_in[15]; const float* be3 = (const float*)d_in[16];
    const float* m3 = (const float*)d_in[17]; const float* v3 = (const float*)d_in[18];

    float* out = (float*)d_out;
    float* newxyz = out;                              // [8][2048][3]
    float* out2 = out + (size_t)BATCH * NPOINT * 3;   // [8][128][2048]

    static bool attr_done = false;
    // (idempotent; done every call is also fine — keep it unconditional for determinism)
    cudaFuncSetAttribute(fps_kernel, cudaFuncAttributeMaxDynamicSharedMemorySize, 3 * NPTS * 4);
    cudaFuncSetAttribute(fused_kernel, cudaFuncAttributeMaxDynamicSharedMemorySize, 57344);
    (void)attr_done;

    prep_kernel<<<1, 128>>>(w1, b1, g1, be1, m1, v1,
                            w2, b2, g2, be2, m2, v2,
                            w3, b3, g3, be3, m3, v3);
    fps_kernel<<<BATCH, 1024, 3 * NPTS * 4>>>(xyz, newxyz);
    fused_kernel<<<BATCH * (NPOINT / 8), 256, 56064>>>(xyz, newxyz, out2);
    (void)in_sizes; (void)n_in; (void)out_size;
}

// round 3
// speedup vs baseline: 1.4071x; 1.4071x over previous
#include <cuda_runtime.h>
#include <math.h>

#define BATCH   8
#define NPTS    8192
#define NPOINT  2048
#define NSAMPLE 32

// ---------------- device scratch (no allocs allowed) ----------------
__device__ float g_W1t[3 * 64];     // [c][o]
__device__ float g_W2t[64 * 64];    // [c][o]
__device__ float g_W3t[64 * 128];   // [c][o]
__device__ float g_B[256];          // b1f[64] | b2f[64] | b3f[128]

// ---------------- packed f32x2 helpers (per-lane IEEE rn, exact) ----------------
__device__ __forceinline__ unsigned long long pk2(float lo, float hi) {
    unsigned long long r;
    asm("mov.b64 %0, {%1,%2};" : "=l"(r) : "f"(lo), "f"(hi));
    return r;
}
__device__ __forceinline__ void upk2(unsigned long long v, float& lo, float& hi) {
    asm("mov.b64 {%0,%1}, %2;" : "=f"(lo), "=f"(hi) : "l"(v));
}
#define ADDX2(o, a, b) asm("add.rn.f32x2 %0, %1, %2;" : "=l"(o) : "l"(a), "l"(b))
#define MULX2(o, a, b) asm("mul.rn.f32x2 %0, %1, %2;" : "=l"(o) : "l"(a), "l"(b))

// ---------------- prep: fold BN into weights ----------------
__global__ void prep_kernel(
    const float* __restrict__ w1, const float* __restrict__ b1, const float* __restrict__ g1,
    const float* __restrict__ be1, const float* __restrict__ m1, const float* __restrict__ v1,
    const float* __restrict__ w2, const float* __restrict__ b2, const float* __restrict__ g2,
    const float* __restrict__ be2, const float* __restrict__ m2, const float* __restrict__ v2,
    const float* __restrict__ w3, const float* __restrict__ b3, const float* __restrict__ g3,
    const float* __restrict__ be3, const float* __restrict__ m3, const float* __restrict__ v3)
{
    int t = threadIdx.x;
    if (t < 64) {
        float s1 = g1[t] / sqrtf(v1[t] + 1e-5f);
        g_B[t] = (b1[t] - m1[t]) * s1 + be1[t];
        for (int c = 0; c < 3; c++) g_W1t[c * 64 + t] = w1[t * 3 + c] * s1;

        float s2 = g2[t] / sqrtf(v2[t] + 1e-5f);
        g_B[64 + t] = (b2[t] - m2[t]) * s2 + be2[t];
        for (int c = 0; c < 64; c++) g_W2t[c * 64 + t] = w2[t * 64 + c] * s2;
    }
    if (t < 128) {
        float s3 = g3[t] / sqrtf(v3[t] + 1e-5f);
        g_B[128 + t] = (b3[t] - m3[t]) * s3 + be3[t];
        for (int c = 0; c < 64; c++) g_W3t[c * 128 + t] = w3[t * 64 + c] * s3;
    }
}

// ---------------- FPS: one CTA per batch ----------------
// Coords packed in registers (f32x2); shared coord mirror for centroid lookup.
// Argmax via REDUX.SYNC on float bits (d>=0) with exact lowest-index tie-break.
// One __syncthreads per iteration (parity double-buffered warp results).
extern __shared__ float fps_sm[];

__global__ __launch_bounds__(1024, 1) void fps_kernel(
    const float* __restrict__ xyz, float* __restrict__ newxyz)
{
    const int b = blockIdx.x;
    const float* P = xyz + (size_t)b * NPTS * 3;
    float* O = newxyz + (size_t)b * NPOINT * 3;
    const int tid = threadIdx.x;
    const int lane = tid & 31, wid = tid >> 5;

    float* shx = fps_sm;              // [8192]
    float* shy = shx + NPTS;          // [8192]
    float* shz = shy + NPTS;          // [8192]

    // point j (j=0..7) of this thread = global index tid + 1024*j
    unsigned long long pxp[4], pyp[4], pzp[4];
    float d[8];
#pragma unroll
    for (int k = 0; k < 4; k++) {
        int p0 = tid + 2048 * k;
        int p1 = p0 + 1024;
        float x0 = P[3 * p0], y0 = P[3 * p0 + 1], z0 = P[3 * p0 + 2];
        float x1 = P[3 * p1], y1 = P[3 * p1 + 1], z1 = P[3 * p1 + 2];
        pxp[k] = pk2(x0, x1); pyp[k] = pk2(y0, y1); pzp[k] = pk2(z0, z1);
        shx[p0] = x0; shy[p0] = y0; shz[p0] = z0;
        shx[p1] = x1; shy[p1] = y1; shz[p1] = z1;
    }

    __shared__ unsigned svv[2][32];
    __shared__ unsigned sii[2][32];

    float cx = P[0], cy = P[1], cz = P[2];
    if (tid == 0) { O[0] = cx; O[1] = cy; O[2] = cz; }

    // init dists vs point 0 (exact rn arithmetic, no FMA)
    {
        unsigned long long ncx = pk2(-cx, -cx), ncy = pk2(-cy, -cy), ncz = pk2(-cz, -cz);
#pragma unroll
        for (int k = 0; k < 4; k++) {
            unsigned long long dx, dy, dz, xx, yy, zz, s;
            ADDX2(dx, pxp[k], ncx); ADDX2(dy, pyp[k], ncy); ADDX2(dz, pzp[k], ncz);
            MULX2(xx, dx, dx); MULX2(yy, dy, dy); MULX2(zz, dz, dz);
            ADDX2(s, xx, yy); ADDX2(s, s, zz);
            upk2(s, d[2 * k], d[2 * k + 1]);
        }
    }
    __syncthreads();   // shared coord mirror ready

    for (int it = 1; it < NPOINT; ++it) {
        const int par = it & 1;
        // ---- update distances (packed, exact) ----
        unsigned long long ncx = pk2(-cx, -cx), ncy = pk2(-cy, -cy), ncz = pk2(-cz, -cz);
#pragma unroll
        for (int k = 0; k < 4; k++) {
            unsigned long long dx, dy, dz, xx, yy, zz, s;
            ADDX2(dx, pxp[k], ncx); ADDX2(dy, pyp[k], ncy); ADDX2(dz, pzp[k], ncz);
            MULX2(xx, dx, dx); MULX2(yy, dy, dy); MULX2(zz, dz, dz);
            ADDX2(s, xx, yy); ADDX2(s, s, zz);
            float s0, s1; upk2(s, s0, s1);
            d[2 * k]     = fminf(d[2 * k], s0);
            d[2 * k + 1] = fminf(d[2 * k + 1], s1);
        }

        // ---- per-thread argmax: 3-level tree, strict > keeps lowest j (= lowest index) ----
        float v0 = d[0]; int j0 = 0; if (d[1] > v0) { v0 = d[1]; j0 = 1; }
        float v1 = d[2]; int j1 = 2; if (d[3] > v1) { v1 = d[3]; j1 = 3; }
        float v2 = d[4]; int j2 = 4; if (d[5] > v2) { v2 = d[5]; j2 = 5; }
        float v3 = d[6]; int j3 = 6; if (d[7] > v3) { v3 = d[7]; j3 = 7; }
        if (v1 > v0) { v0 = v1; j0 = j1; }
        if (v3 > v2) { v2 = v3; j2 = j3; }
        if (v2 > v0) { v0 = v2; j0 = j2; }
        unsigned key = __float_as_uint(v0);          // d >= 0: bits order == float order
        unsigned bi  = (unsigned)(tid + (j0 << 10));

        // ---- warp argmax via redux (value max, then min index among ties) ----
        unsigned wmax = __reduce_max_sync(0xffffffffu, key);
        unsigned cand = (key == wmax) ? bi : 0xffffffffu;
        unsigned wbi  = __reduce_min_sync(0xffffffffu, cand);
        if (lane == 0) { svv[par][wid] = wmax; sii[par][wid] = wbi; }
        __syncthreads();

        // ---- block argmax: every warp redundantly reduces the 32 warp results ----
        unsigned k2 = svv[par][lane];
        unsigned i2 = sii[par][lane];
        unsigned m2 = __reduce_max_sync(0xffffffffu, k2);
        unsigned c2 = (k2 == m2) ? i2 : 0xffffffffu;
        unsigned ci = __reduce_min_sync(0xffffffffu, c2);

        cx = shx[ci]; cy = shy[ci]; cz = shz[ci];
        if (tid == 0) { float* o = O + 3 * it; o[0] = cx; o[1] = cy; o[2] = cz; }
    }
}

// ---------------- fused ball-query + MLP + maxpool (unchanged) ----------------
extern __shared__ float fus_sm[];

__global__ __launch_bounds__(256) void fused_kernel(
    const float* __restrict__ xyz, const float* __restrict__ newxyz,
    float* __restrict__ out2)
{
    float* W2t   = fus_sm;                  // 64*64
    float* W3t   = W2t + 64 * 64;           // 64*128
    float* W1t   = W3t + 64 * 128;          // 3*64
    float* Bsh   = W1t + 192;               // 256
    float* stage = Bsh + 256;               // 128*8
    int*   nb    = (int*)(stage + 128 * 8); // 8*32

    const int tid = threadIdx.x;
    for (int i = tid; i < 64 * 64; i += 256)  W2t[i] = g_W2t[i];
    for (int i = tid; i < 64 * 128; i += 256) W3t[i] = g_W3t[i];
    if (tid < 192) W1t[tid] = g_W1t[tid];
    if (tid < 256) Bsh[tid] = g_B[tid];
    __syncthreads();

    const int w = tid >> 5, lane = tid & 31;
    const int b = blockIdx.x >> 8;
    const int m0 = (blockIdx.x & 255) * 8;
    const int m = m0 + w;

    const float* P = xyz + (size_t)b * NPTS * 3;
    const float* C = newxyz + ((size_t)b * NPOINT + m) * 3;
    const float cx = C[0], cy = C[1], cz = C[2];

    const float R2 = (float)(0.2 * 0.2);
    int* mynb = nb + w * 32;
    int cnt = 0;
    for (int base = 0; base < NPTS && cnt < NSAMPLE; base += 32) {
        int p = base + lane;
        float x = P[3 * p], y = P[3 * p + 1], z = P[3 * p + 2];
        float dx = __fadd_rn(x, -cx), dy = __fadd_rn(y, -cy), dz = __fadd_rn(z, -cz);
        float s = __fadd_rn(__fadd_rn(__fmul_rn(dx, dx), __fmul_rn(dy, dy)), __fmul_rn(dz, dz));
        bool in = (s <= R2);
        unsigned msk = __ballot_sync(0xffffffffu, in);
        int pos = cnt + __popc(msk & ((1u << lane) - 1u));
        if (in && pos < NSAMPLE) mynb[pos] = p;
        cnt += __popc(msk);
    }
    __syncwarp();
    int src = (cnt >= NSAMPLE) ? lane : (lane % cnt);
    int g = mynb[src];

    float gx = P[3 * g] - cx, gy = P[3 * g + 1] - cy, gz = P[3 * g + 2] - cz;

    float h1[64];
#pragma unroll
    for (int o = 0; o < 64; o++) h1[o] = fmaf(gx, W1t[o], Bsh[o]);
#pragma unroll
    for (int o = 0; o < 64; o++) h1[o] = fmaf(gy, W1t[64 + o], h1[o]);
#pragma unroll
    for (int o = 0; o < 64; o++) h1[o] = fmaxf(fmaf(gz, W1t[128 + o], h1[o]), 0.0f);

    float h2[64];
#pragma unroll
    for (int o = 0; o < 64; o++) h2[o] = Bsh[64 + o];
#pragma unroll
    for (int c = 0; c < 64; c++) {
        float hc = h1[c];
        const float4* wr = (const float4*)(W2t + c * 64);
#pragma unroll
        for (int q = 0; q < 16; q++) {
            float4 wv = wr[q];
            h2[4 * q + 0] = fmaf(hc, wv.x, h2[4 * q + 0]);
            h2[4 * q + 1] = fmaf(hc, wv.y, h2[4 * q + 1]);
            h2[4 * q + 2] = fmaf(hc, wv.z, h2[4 * q + 2]);
            h2[4 * q + 3] = fmaf(hc, wv.w, h2[4 * q + 3]);
        }
    }
#pragma unroll
    for (int o = 0; o < 64; o++) h2[o] = fmaxf(h2[o], 0.0f);

#pragma unroll
    for (int half = 0; half < 2; half++) {
        float acc[64];
#pragma unroll
        for (int o = 0; o < 64; o++) acc[o] = Bsh[128 + half * 64 + o];
#pragma unroll
        for (int c = 0; c < 64; c++) {
            float hc = h2[c];
            const float4* wr = (const float4*)(W3t + c * 128 + half * 64);
#pragma unroll
            for (int q = 0; q < 16; q++) {
                float4 wv = wr[q];
                acc[4 * q + 0] = fmaf(hc, wv.x, acc[4 * q + 0]);
                acc[4 * q + 1] = fmaf(hc, wv.y, acc[4 * q + 1]);
                acc[4 * q + 2] = fmaf(hc, wv.z, acc[4 * q + 2]);
                acc[4 * q + 3] = fmaf(hc, wv.w, acc[4 * q + 3]);
            }
        }
#pragma unroll
        for (int o = 0; o < 64; o++) acc[o] = fmaxf(acc[o], 0.0f);
#pragma unroll
        for (int off = 16; off >= 1; off >>= 1) {
#pragma unroll
            for (int o = 0; o < 64; o++)
                acc[o] = fmaxf(acc[o], __shfl_down_sync(0xffffffffu, acc[o], off));
        }
        if (lane == 0) {
#pragma unroll
            for (int o = 0; o < 64; o++) stage[(half * 64 + o) * 8 + w] = acc[o];
        }
    }
    __syncthreads();

    {
        int ch = tid >> 1, part = tid & 1;
        float4 v = ((const float4*)stage)[tid];
        *(float4*)(out2 + ((size_t)(b * 128 + ch)) * NPOINT + m0 + part * 4) = v;
    }
}

// ---------------- launch ----------------
extern "C" void kernel_launch(void* const* d_in, const int* in_sizes, int n_in,
                              void* d_out, int out_size)
{
    const float* xyz = (const float*)d_in[0];
    const float* w1 = (const float*)d_in[1];  const float* b1 = (const float*)d_in[2];
    const float* g1 = (const float*)d_in[3];  const float* be1 = (const float*)d_in[4];
    const float* m1 = (const float*)d_in[5];  const float* v1 = (const float*)d_in[6];
    const float* w2 = (const float*)d_in[7];  const float* b2 = (const float*)d_in[8];
    const float* g2 = (const float*)d_in[9];  const float* be2 = (const float*)d_in[10];
    const float* m2 = (const float*)d_in[11]; const float* v2 = (const float*)d_in[12];
    const float* w3 = (const float*)d_in[13]; const float* b3 = (const float*)d_in[14];
    const float* g3 = (const float*)d_in[15]; const float* be3 = (const float*)d_in[16];
    const float* m3 = (const float*)d_in[17]; const float* v3 = (const float*)d_in[18];

    float* out = (float*)d_out;
    float* newxyz = out;                              // [8][2048][3]
    float* out2 = out + (size_t)BATCH * NPOINT * 3;   // [8][128][2048]

    cudaFuncSetAttribute(fps_kernel, cudaFuncAttributeMaxDynamicSharedMemorySize, 3 * NPTS * 4);
    cudaFuncSetAttribute(fused_kernel, cudaFuncAttributeMaxDynamicSharedMemorySize, 57344);

    prep_kernel<<<1, 128>>>(w1, b1, g1, be1, m1, v1,
                            w2, b2, g2, be2, m2, v2,
                            w3, b3, g3, be3, m3, v3);
    fps_kernel<<<BATCH, 1024, 3 * NPTS * 4>>>(xyz, newxyz);
    fused_kernel<<<BATCH * (NPOINT / 8), 256, 56064>>>(xyz, newxyz, out2);
    (void)in_sizes; (void)n_in; (void)out_size;
}

// round 4
// speedup vs baseline: 1.5063x; 1.0705x over previous
#include <cuda_runtime.h>
#include <math.h>

#define BATCH   8
#define NPTS    8192
#define NPOINT  2048
#define NSAMPLE 32

// ---------------- device scratch (no allocs allowed) ----------------
__device__ float g_W1t[3 * 64];     // [c][o]
__device__ float g_W2t[64 * 64];    // [c][o]
__device__ float g_W3t[64 * 128];   // [c][o]
__device__ float g_B[256];          // b1f[64] | b2f[64] | b3f[128]

// ---------------- prep: fold BN into weights ----------------
__global__ void prep_kernel(
    const float* __restrict__ w1, const float* __restrict__ b1, const float* __restrict__ g1,
    const float* __restrict__ be1, const float* __restrict__ m1, const float* __restrict__ v1,
    const float* __restrict__ w2, const float* __restrict__ b2, const float* __restrict__ g2,
    const float* __restrict__ be2, const float* __restrict__ m2, const float* __restrict__ v2,
    const float* __restrict__ w3, const float* __restrict__ b3, const float* __restrict__ g3,
    const float* __restrict__ be3, const float* __restrict__ m3, const float* __restrict__ v3)
{
    int t = threadIdx.x;
    if (t < 64) {
        float s1 = g1[t] / sqrtf(v1[t] + 1e-5f);
        g_B[t] = (b1[t] - m1[t]) * s1 + be1[t];
        for (int c = 0; c < 3; c++) g_W1t[c * 64 + t] = w1[t * 3 + c] * s1;

        float s2 = g2[t] / sqrtf(v2[t] + 1e-5f);
        g_B[64 + t] = (b2[t] - m2[t]) * s2 + be2[t];
        for (int c = 0; c < 64; c++) g_W2t[c * 64 + t] = w2[t * 64 + c] * s2;
    }
    if (t < 128) {
        float s3 = g3[t] / sqrtf(v3[t] + 1e-5f);
        g_B[128 + t] = (b3[t] - m3[t]) * s3 + be3[t];
        for (int c = 0; c < 64; c++) g_W3t[c * 128 + t] = w3[t * 64 + c] * s3;
    }
}

// ---------------- FPS with Morton-sorted lazy updates ----------------
// shared: shx/shy/shz (orig-indexed, 96KB) | hist (16KB) | order (32KB)
extern __shared__ float fps_sm[];

__device__ __forceinline__ unsigned spread3(unsigned v) {   // 4-bit -> bits {0,3,6,9}
    v = (v | (v << 4)) & 0x0C3u;
    v = (v | (v << 2)) & 0x249u;
    return v;
}

__global__ __launch_bounds__(1024, 1) void fps_kernel(
    const float* __restrict__ xyz, float* __restrict__ newxyz)
{
    const int b = blockIdx.x;
    const float* P = xyz + (size_t)b * NPTS * 3;
    float* O = newxyz + (size_t)b * NPOINT * 3;
    const int tid = threadIdx.x;
    const int lane = tid & 31, wid = tid >> 5;

    float* shx = fps_sm;                    // [8192] original index
    float* shy = shx + NPTS;
    float* shz = shy + NPTS;
    int*   hist  = (int*)(shz + NPTS);      // [4096]
    int*   order = hist + 4096;             // [8192]

    __shared__ unsigned svv[2][32];
    __shared__ unsigned sii[2][32];
    __shared__ int wsums[32];

    // ---- load, mirror to shared, compute Morton keys ----
    unsigned key[8];
#pragma unroll
    for (int k = 0; k < 8; k++) {
        int p = tid + 1024 * k;
        float x = P[3 * p], y = P[3 * p + 1], z = P[3 * p + 2];
        shx[p] = x; shy[p] = y; shz[p] = z;
        int ix = min(15, max(0, (int)(x * 16.0f)));
        int iy = min(15, max(0, (int)(y * 16.0f)));
        int iz = min(15, max(0, (int)(z * 16.0f)));
        key[k] = spread3((unsigned)ix) | (spread3((unsigned)iy) << 1) | (spread3((unsigned)iz) << 2);
    }
    for (int i = tid; i < 4096; i += 1024) hist[i] = 0;
    __syncthreads();
#pragma unroll
    for (int k = 0; k < 8; k++) atomicAdd(&hist[key[k]], 1);
    __syncthreads();

    // ---- exclusive scan over 4096 bins (4 per thread) ----
    int h0 = hist[4 * tid], h1 = hist[4 * tid + 1], h2 = hist[4 * tid + 2], h3 = hist[4 * tid + 3];
    int tsum = h0 + h1 + h2 + h3;
    int inc = tsum;
#pragma unroll
    for (int off = 1; off < 32; off <<= 1) {
        int n = __shfl_up_sync(0xffffffffu, inc, off);
        if (lane >= off) inc += n;
    }
    if (lane == 31) wsums[wid] = inc;
    __syncthreads();
    if (wid == 0) {
        int s = wsums[lane];
        int i2 = s;
#pragma unroll
        for (int off = 1; off < 32; off <<= 1) {
            int n = __shfl_up_sync(0xffffffffu, i2, off);
            if (lane >= off) i2 += n;
        }
        wsums[lane] = i2 - s;
    }
    __syncthreads();
    {
        int run = wsums[wid] + (inc - tsum);
        hist[4 * tid] = run; run += h0;
        hist[4 * tid + 1] = run; run += h1;
        hist[4 * tid + 2] = run; run += h2;
        hist[4 * tid + 3] = run;
    }
    __syncthreads();

    // ---- scatter original indices into sorted order ----
#pragma unroll
    for (int k = 0; k < 8; k++) {
        int pos = atomicAdd(&hist[key[k]], 1);
        order[pos] = tid + 1024 * k;
    }
    __syncthreads();

    // ---- gather my 8 sorted points: orig indices, bbox, init dists vs P[0] ----
    float cx = P[0], cy = P[1], cz = P[2];
    if (tid == 0) { O[0] = cx; O[1] = cy; O[2] = cz; }

    int orig[8];
    float d[8];
    float bxl = 1e30f, bxh = -1e30f, byl = 1e30f, byh = -1e30f, bzl = 1e30f, bzh = -1e30f;
#pragma unroll
    for (int j = 0; j < 8; j++) {
        int o = order[8 * tid + j];
        orig[j] = o;
        float x = shx[o], y = shy[o], z = shz[o];
        bxl = fminf(bxl, x); bxh = fmaxf(bxh, x);
        byl = fminf(byl, y); byh = fmaxf(byh, y);
        bzl = fminf(bzl, z); bzh = fmaxf(bzh, z);
        float dx = __fadd_rn(x, -cx), dy = __fadd_rn(y, -cy), dz = __fadd_rn(z, -cz);
        d[j] = __fadd_rn(__fadd_rn(__fmul_rn(dx, dx), __fmul_rn(dy, dy)), __fmul_rn(dz, dz));
    }
    const float bcx = (bxl + bxh) * 0.5f, bex = (bxh - bxl) * 0.5f;
    const float bcy = (byl + byh) * 0.5f, bey = (byh - byl) * 0.5f;
    const float bcz = (bzl + bzh) * 0.5f, bez = (bzh - bzl) * 0.5f;

    // cached per-thread argmax (value + lowest original index among ties)
    float vmax; unsigned bidx;
    {
        float v = d[0];
#pragma unroll
        for (int j = 1; j < 8; j++) v = fmaxf(v, d[j]);
        unsigned bi = 0xffffffffu;
#pragma unroll
        for (int j = 0; j < 8; j++) if (d[j] == v) bi = min(bi, (unsigned)orig[j]);
        vmax = v; bidx = bi;
    }

    for (int it = 1; it < NPOINT; ++it) {
        const int par = it & 1;

        // ---- conservative skip test: can centroid c change any of my d's? ----
        float tx = fmaxf(fabsf(cx - bcx) - bex, 0.0f);
        float ty = fmaxf(fabsf(cy - bcy) - bey, 0.0f);
        float tz = fmaxf(fabsf(cz - bcz) - bez, 0.0f);
        float bound = tx * tx + ty * ty + tz * tz;
        if (bound < vmax * 1.0002f) {
            // ---- full exact update of my 8 points ----
#pragma unroll
            for (int j = 0; j < 8; j++) {
                int o = orig[j];
                float dx = __fadd_rn(shx[o], -cx);
                float dy = __fadd_rn(shy[o], -cy);
                float dz = __fadd_rn(shz[o], -cz);
                float s = __fadd_rn(__fadd_rn(__fmul_rn(dx, dx), __fmul_rn(dy, dy)),
                                    __fmul_rn(dz, dz));
                d[j] = fminf(d[j], s);
            }
            float v = d[0];
#pragma unroll
            for (int j = 1; j < 8; j++) v = fmaxf(v, d[j]);
            unsigned bi = 0xffffffffu;
#pragma unroll
            for (int j = 0; j < 8; j++) if (d[j] == v) bi = min(bi, (unsigned)orig[j]);
            vmax = v; bidx = bi;
        }

        // ---- warp argmax via redux (d>=0: float bits order as uint) ----
        unsigned keyv = __float_as_uint(vmax);
        unsigned wmax = __reduce_max_sync(0xffffffffu, keyv);
        unsigned cand = (keyv == wmax) ? bidx : 0xffffffffu;
        unsigned wbi  = __reduce_min_sync(0xffffffffu, cand);
        if (lane == 0) { svv[par][wid] = wmax; sii[par][wid] = wbi; }
        __syncthreads();

        // ---- block argmax: every warp redundantly reduces 32 warp results ----
        unsigned k2 = svv[par][lane];
        unsigned i2 = sii[par][lane];
        unsigned m2 = __reduce_max_sync(0xffffffffu, k2);
        unsigned c2 = (k2 == m2) ? i2 : 0xffffffffu;
        unsigned ci = __reduce_min_sync(0xffffffffu, c2);

        cx = shx[ci]; cy = shy[ci]; cz = shz[ci];
        if (tid == 0) { float* o = O + 3 * it; o[0] = cx; o[1] = cy; o[2] = cz; }
    }
}

// ---------------- fused ball-query + MLP + maxpool (unchanged) ----------------
extern __shared__ float fus_sm[];

__global__ __launch_bounds__(256) void fused_kernel(
    const float* __restrict__ xyz, const float* __restrict__ newxyz,
    float* __restrict__ out2)
{
    float* W2t   = fus_sm;                  // 64*64
    float* W3t   = W2t + 64 * 64;           // 64*128
    float* W1t   = W3t + 64 * 128;          // 3*64
    float* Bsh   = W1t + 192;               // 256
    float* stage = Bsh + 256;               // 128*8
    int*   nb    = (int*)(stage + 128 * 8); // 8*32

    const int tid = threadIdx.x;
    for (int i = tid; i < 64 * 64; i += 256)  W2t[i] = g_W2t[i];
    for (int i = tid; i < 64 * 128; i += 256) W3t[i] = g_W3t[i];
    if (tid < 192) W1t[tid] = g_W1t[tid];
    if (tid < 256) Bsh[tid] = g_B[tid];
    __syncthreads();

    const int w = tid >> 5, lane = tid & 31;
    const int b = blockIdx.x >> 8;
    const int m0 = (blockIdx.x & 255) * 8;
    const int m = m0 + w;

    const float* P = xyz + (size_t)b * NPTS * 3;
    const float* C = newxyz + ((size_t)b * NPOINT + m) * 3;
    const float cx = C[0], cy = C[1], cz = C[2];

    const float R2 = (float)(0.2 * 0.2);
    int* mynb = nb + w * 32;
    int cnt = 0;
    for (int base = 0; base < NPTS && cnt < NSAMPLE; base += 32) {
        int p = base + lane;
        float x = P[3 * p], y = P[3 * p + 1], z = P[3 * p + 2];
        float dx = __fadd_rn(x, -cx), dy = __fadd_rn(y, -cy), dz = __fadd_rn(z, -cz);
        float s = __fadd_rn(__fadd_rn(__fmul_rn(dx, dx), __fmul_rn(dy, dy)), __fmul_rn(dz, dz));
        bool in = (s <= R2);
        unsigned msk = __ballot_sync(0xffffffffu, in);
        int pos = cnt + __popc(msk & ((1u << lane) - 1u));
        if (in && pos < NSAMPLE) mynb[pos] = p;
        cnt += __popc(msk);
    }
    __syncwarp();
    int src = (cnt >= NSAMPLE) ? lane : (lane % cnt);
    int g = mynb[src];

    float gx = P[3 * g] - cx, gy = P[3 * g + 1] - cy, gz = P[3 * g + 2] - cz;

    float h1[64];
#pragma unroll
    for (int o = 0; o < 64; o++) h1[o] = fmaf(gx, W1t[o], Bsh[o]);
#pragma unroll
    for (int o = 0; o < 64; o++) h1[o] = fmaf(gy, W1t[64 + o], h1[o]);
#pragma unroll
    for (int o = 0; o < 64; o++) h1[o] = fmaxf(fmaf(gz, W1t[128 + o], h1[o]), 0.0f);

    float h2[64];
#pragma unroll
    for (int o = 0; o < 64; o++) h2[o] = Bsh[64 + o];
#pragma unroll
    for (int c = 0; c < 64; c++) {
        float hc = h1[c];
        const float4* wr = (const float4*)(W2t + c * 64);
#pragma unroll
        for (int q = 0; q < 16; q++) {
            float4 wv = wr[q];
            h2[4 * q + 0] = fmaf(hc, wv.x, h2[4 * q + 0]);
            h2[4 * q + 1] = fmaf(hc, wv.y, h2[4 * q + 1]);
            h2[4 * q + 2] = fmaf(hc, wv.z, h2[4 * q + 2]);
            h2[4 * q + 3] = fmaf(hc, wv.w, h2[4 * q + 3]);
        }
    }
#pragma unroll
    for (int o = 0; o < 64; o++) h2[o] = fmaxf(h2[o], 0.0f);

#pragma unroll
    for (int half = 0; half < 2; half++) {
        float acc[64];
#pragma unroll
        for (int o = 0; o < 64; o++) acc[o] = Bsh[128 + half * 64 + o];
#pragma unroll
        for (int c = 0; c < 64; c++) {
            float hc = h2[c];
            const float4* wr = (const float4*)(W3t + c * 128 + half * 64);
#pragma unroll
            for (int q = 0; q < 16; q++) {
                float4 wv = wr[q];
                acc[4 * q + 0] = fmaf(hc, wv.x, acc[4 * q + 0]);
                acc[4 * q + 1] = fmaf(hc, wv.y, acc[4 * q + 1]);
                acc[4 * q + 2] = fmaf(hc, wv.z, acc[4 * q + 2]);
                acc[4 * q + 3] = fmaf(hc, wv.w, acc[4 * q + 3]);
            }
        }
#pragma unroll
        for (int o = 0; o < 64; o++) acc[o] = fmaxf(acc[o], 0.0f);
#pragma unroll
        for (int off = 16; off >= 1; off >>= 1) {
#pragma unroll
            for (int o = 0; o < 64; o++)
                acc[o] = fmaxf(acc[o], __shfl_down_sync(0xffffffffu, acc[o], off));
        }
        if (lane == 0) {
#pragma unroll
            for (int o = 0; o < 64; o++) stage[(half * 64 + o) * 8 + w] = acc[o];
        }
    }
    __syncthreads();

    {
        int ch = tid >> 1, part = tid & 1;
        float4 v = ((const float4*)stage)[tid];
        *(float4*)(out2 + ((size_t)(b * 128 + ch)) * NPOINT + m0 + part * 4) = v;
    }
}

// ---------------- launch ----------------
extern "C" void kernel_launch(void* const* d_in, const int* in_sizes, int n_in,
                              void* d_out, int out_size)
{
    const float* xyz = (const float*)d_in[0];
    const float* w1 = (const float*)d_in[1];  const float* b1 = (const float*)d_in[2];
    const float* g1 = (const float*)d_in[3];  const float* be1 = (const float*)d_in[4];
    const float* m1 = (const float*)d_in[5];  const float* v1 = (const float*)d_in[6];
    const float* w2 = (const float*)d_in[7];  const float* b2 = (const float*)d_in[8];
    const float* g2 = (const float*)d_in[9];  const float* be2 = (const float*)d_in[10];
    const float* m2 = (const float*)d_in[11]; const float* v2 = (const float*)d_in[12];
    const float* w3 = (const float*)d_in[13]; const float* b3 = (const float*)d_in[14];
    const float* g3 = (const float*)d_in[15]; const float* be3 = (const float*)d_in[16];
    const float* m3 = (const float*)d_in[17]; const float* v3 = (const float*)d_in[18];

    float* out = (float*)d_out;
    float* newxyz = out;                              // [8][2048][3]
    float* out2 = out + (size_t)BATCH * NPOINT * 3;   // [8][128][2048]

    const int FPS_SMEM = (NPTS * 3 + 4096 + NPTS) * 4;   // 147456 bytes
    cudaFuncSetAttribute(fps_kernel, cudaFuncAttributeMaxDynamicSharedMemorySize, FPS_SMEM);
    cudaFuncSetAttribute(fused_kernel, cudaFuncAttributeMaxDynamicSharedMemorySize, 57344);

    prep_kernel<<<1, 128>>>(w1, b1, g1, be1, m1, v1,
                            w2, b2, g2, be2, m2, v2,
                            w3, b3, g3, be3, m3, v3);
    fps_kernel<<<BATCH, 1024, FPS_SMEM>>>(xyz, newxyz);
    fused_kernel<<<BATCH * (NPOINT / 8), 256, 56064>>>(xyz, newxyz, out2);
    (void)in_sizes; (void)n_in; (void)out_size;
}